// round 7
// baseline (speedup 1.0000x reference)
#include <cuda_runtime.h>

#define Nn 150000
#define Ee 4800000
#define NOUT 68
#define NW2 ((Nn + 15) / 16)     // 9375 words, 2 bits per node
#define CAP68 8192
#define CAP2 131072

// ---------------- device scratch (no allocation allowed) ----------------
__device__ __align__(16) float4 g0v[Nn * 2];   // augmented input features (8 dims)
__device__ __align__(16) float4 g1v[Nn * 2];   // S1sum -> layer-1 mean (masked nodes)
__device__ __align__(16) float4 g2v[Nn * 2];   // S2sum -> layer-2 mean (masked nodes)
__device__ int   cntv[Nn];        // in-degree (exact at masked nodes)
__device__ int   zcv[Nn];         // cold-path: # zero-degree in-neighbors
__device__ float d2v[Nn];         // const-column after 2 aggregations
__device__ int   any_zero;
__device__ unsigned bits12[NW2];  // plane1 (bit 2k): S1; plane2 (bit 2k+1): S2
__device__ int2  l68[CAP68];      // edges with dst < 68
__device__ int   n68;
__device__ int2  l2v[CAP2];       // edges with dst in S1 u [0,68)
__device__ int   n2;
__device__ float out_acc[NOUT * 9];
__device__ float Cmat[4 * 27];

__device__ __forceinline__ bool tb1g(int v) {
    return (v < NOUT) || ((__ldg(&bits12[v >> 4]) >> ((v & 15) * 2)) & 1u);
}
__device__ __forceinline__ bool tb2g(int v) {
    return (__ldg(&bits12[v >> 4]) >> ((v & 15) * 2 + 1)) & 1u;
}
__device__ __forceinline__ void red_v4(float* addr, float4 v) {
    asm volatile("red.global.add.v4.f32 [%0], {%1,%2,%3,%4};"
                 :: "l"(addr), "f"(v.x), "f"(v.y), "f"(v.z), "f"(v.w)
                 : "memory");
}

// ---------------- K0: collapsed 9x3 weight matrices ----------------
__global__ void build_cmat(const float* __restrict__ Wl1, const float* __restrict__ Wr1,
                           const float* __restrict__ b1,
                           const float* __restrict__ Wl2, const float* __restrict__ Wr2,
                           const float* __restrict__ b2,
                           const float* __restrict__ Wl3, const float* __restrict__ Wr3,
                           const float* __restrict__ b3) {
    __shared__ float T0[9 * 17], T1[9 * 17];
    __shared__ float U0[9 * 17], U1[9 * 17], U2[9 * 17];
    int t = threadIdx.x;
    int r = t / 17, c = t % 17;
    if (t < 9 * 17) {
        float wl, wr;
        if (r < 8) {
            wl = (c < 16) ? Wl1[r * 16 + c] : 0.f;
            wr = (c < 16) ? Wr1[r * 16 + c] : 0.f;
        } else {
            wl = 0.f;
            wr = (c < 16) ? b1[c] : 1.f;
        }
        T0[t] = wr;
        T1[t] = wl;
    }
    __syncthreads();
    if (t < 9 * 17) {
        float a0 = 0.f, a1 = 0.f, a2 = 0.f;
        for (int k = 0; k < 17; k++) {
            float wr2 = (k < 16) ? ((c < 16) ? Wr2[k * 16 + c] : 0.f)
                                 : ((c < 16) ? b2[c] : 1.f);
            float wl2 = (k < 16 && c < 16) ? Wl2[k * 16 + c] : 0.f;
            float t0 = T0[r * 17 + k], t1 = T1[r * 17 + k];
            a0 += t0 * wr2;
            a1 += t1 * wr2 + t0 * wl2;
            a2 += t1 * wl2;
        }
        U0[t] = a0; U1[t] = a1; U2[t] = a2;
    }
    __syncthreads();
    if (t < 27) {
        int rr = t / 3, cc = t % 3;
        float c0 = 0.f, c1 = 0.f, c2 = 0.f, c3 = 0.f;
        for (int k = 0; k < 17; k++) {
            float wr3 = (k < 16) ? Wr3[k * 3 + cc] : b3[cc];
            float wl3 = (k < 16) ? Wl3[k * 3 + cc] : 0.f;
            float u0 = U0[rr * 17 + k], u1 = U1[rr * 17 + k], u2 = U2[rr * 17 + k];
            c0 += u0 * wr3;
            c1 += u1 * wr3 + u0 * wl3;
            c2 += u2 * wr3 + u1 * wl3;
            c3 += u2 * wl3;
        }
        Cmat[0 * 27 + t] = c0;
        Cmat[1 * 27 + t] = c1;
        Cmat[2 * 27 + t] = c2;
        Cmat[3 * 27 + t] = c3;
    }
}

// ---------------- K1: init everything + compute g0 ----------------
__global__ void init_kernel(const float* __restrict__ x,
                            const float* __restrict__ w_pos,
                            const float* __restrict__ b_pos) {
    int i = blockIdx.x * blockDim.x + threadIdx.x;
    if (i >= Nn) return;
    cntv[i] = 0; zcv[i] = 0;
    float4 z = make_float4(0.f, 0.f, 0.f, 0.f);
    g1v[i * 2] = z; g1v[i * 2 + 1] = z;
    g2v[i * 2] = z; g2v[i * 2 + 1] = z;
    if (i < NW2) bits12[i] = 0u;
    if (i < NOUT) {
#pragma unroll
        for (int j = 0; j < 9; j++) out_acc[i * 9 + j] = 0.f;
    }
    if (i == 0) { n68 = 0; n2 = 0; any_zero = 0; }
    float fi = (float)i;
    float g[8];
    g[0] = x[i * 3 + 0]; g[1] = x[i * 3 + 1]; g[2] = x[i * 3 + 2];
#pragma unroll
    for (int p = 0; p < 5; p++) g[3 + p] = tanhf(fi * __ldg(&w_pos[p]) + __ldg(&b_pos[p]));
    g0v[i * 2 + 0] = *(float4*)&g[0];
    g0v[i * 2 + 1] = *(float4*)&g[4];
}

// ---------------- K2: scan1 -- mark plane1, compact dst<68 (probe-free test) ----
__global__ void scan1(const int* __restrict__ ei) {
    int t = blockIdx.x * blockDim.x + threadIdx.x;
    int base = t * 4;
    if (base >= Ee) return;
    int4 d4 = __ldg((const int4*)&ei[Ee + base]);
    int dd[4] = { d4.x, d4.y, d4.z, d4.w };
    bool anyhit = (dd[0] < NOUT) | (dd[1] < NOUT) | (dd[2] < NOUT) | (dd[3] < NOUT);
    if (!anyhit) return;
    int4 s4 = __ldg((const int4*)&ei[base]);
    int ss[4] = { s4.x, s4.y, s4.z, s4.w };
#pragma unroll
    for (int k = 0; k < 4; k++) {
        if (dd[k] < NOUT) {
            int s = ss[k];
            unsigned m = 1u << ((s & 15) * 2);
            if (!(__ldg(&bits12[s >> 4]) & m)) atomicOr(&bits12[s >> 4], m);
            int p = atomicAdd(&n68, 1);
            if (p < CAP68) l68[p] = make_int2(s, dd[k]);
        }
    }
}

// ---------------- K3: scan2 -- smem-bitmap probe, mark plane2, compact l2v -----
__global__ __launch_bounds__(1024) void scan2s(const int* __restrict__ ei) {
    __shared__ unsigned smb[NW2];      // 37.5 KB
    for (int j = threadIdx.x; j < NW2; j += 1024) smb[j] = bits12[j];
    __syncthreads();
    int t = blockIdx.x * 1024 + threadIdx.x;
    int base = t * 4;
    int lane = threadIdx.x & 31;
    bool valid = (base < Ee);
    int dd[4] = { 0, 0, 0, 0 };
    bool hh[4] = { false, false, false, false };
    if (valid) {
        int4 d4 = __ldg((const int4*)&ei[Ee + base]);
        dd[0] = d4.x; dd[1] = d4.y; dd[2] = d4.z; dd[3] = d4.w;
#pragma unroll
        for (int k = 0; k < 4; k++) {
            int d = dd[k];
            hh[k] = (d < NOUT) || ((smb[d >> 4] >> ((d & 15) * 2)) & 1u);
        }
    }
    bool any = hh[0] | hh[1] | hh[2] | hh[3];
    if (__ballot_sync(0xffffffffu, any) == 0) return;   // warp-uniform exit
    int ss[4] = { 0, 0, 0, 0 };
    if (any) {
        int4 s4 = __ldg((const int4*)&ei[base]);
        ss[0] = s4.x; ss[1] = s4.y; ss[2] = s4.z; ss[3] = s4.w;
    }
#pragma unroll
    for (int k = 0; k < 4; k++) {
        unsigned bal = __ballot_sync(0xffffffffu, hh[k]);
        if (bal) {
            int leader = __ffs(bal) - 1;
            int pos0 = 0;
            if (lane == leader) pos0 = atomicAdd(&n2, __popc(bal));
            pos0 = __shfl_sync(0xffffffffu, pos0, leader);
            if (hh[k]) {
                int p = pos0 + __popc(bal & ((1u << lane) - 1u));
                if (p < CAP2) l2v[p] = make_int2(ss[k], dd[k]);
                int s = ss[k];
                unsigned m = 2u << ((s & 15) * 2);
                if (!(__ldg(&bits12[s >> 4]) & m)) atomicOr(&bits12[s >> 4], m);
            }
        }
    }
}

// ---------------- K4: scan3 -- smem-bitmap, masked count + masked g0 scatter ----
__global__ __launch_bounds__(1024) void scan3s(const int* __restrict__ ei) {
    __shared__ unsigned smb[NW2];      // both planes final
    for (int j = threadIdx.x; j < NW2; j += 1024) smb[j] = bits12[j];
    __syncthreads();
    int t = blockIdx.x * 1024 + threadIdx.x;
    int base = t * 4;
    if (base >= Ee) return;
    int4 d4 = __ldg((const int4*)&ei[Ee + base]);
    int dd[4] = { d4.x, d4.y, d4.z, d4.w };
    bool ff[4], cc[4];
#pragma unroll
    for (int k = 0; k < 4; k++) {
        int d = dd[k];
        unsigned pr = (smb[d >> 4] >> ((d & 15) * 2)) & 3u;
        ff[k] = ((pr >> 1) & 1u) || (d < NOUT);
        cc[k] = ff[k] || (pr & 1u);
    }
    if (!(cc[0] | cc[1] | cc[2] | cc[3])) return;
    int4 s4 = __ldg((const int4*)&ei[base]);
    int ss[4] = { s4.x, s4.y, s4.z, s4.w };
#pragma unroll
    for (int k = 0; k < 4; k++) {
        if (cc[k]) atomicAdd(&cntv[dd[k]], 1);
        if (ff[k]) {
            int s = ss[k], d = dd[k];
            float4 a = __ldg(&g0v[s * 2]);
            float4 b = __ldg(&g0v[s * 2 + 1]);
            red_v4((float*)&g1v[d * 2], a);
            red_v4((float*)&g1v[d * 2 + 1], b);
        }
    }
}

// ---------------- K5: norm1 -- g1 = S1sum/cnt at plane2|O; d2 default ----------
__global__ void norm1() {
    int i = blockIdx.x * blockDim.x + threadIdx.x;
    if (i >= Nn) return;
    unsigned pr = (__ldg(&bits12[i >> 4]) >> ((i & 15) * 2)) & 3u;
    bool b2m = (pr >> 1) & 1u;
    int c = cntv[i];
    if (b2m || (i < NOUT)) {
        if (b2m && c == 0) any_zero = 1;
        float inv = 1.f / (float)max(c, 1);
        float4 a = g1v[i * 2], b = g1v[i * 2 + 1];
        a.x *= inv; a.y *= inv; a.z *= inv; a.w *= inv;
        b.x *= inv; b.y *= inv; b.z *= inv; b.w *= inv;
        g1v[i * 2] = a; g1v[i * 2 + 1] = b;
    }
    if ((pr & 1u) || (i < NOUT)) d2v[i] = (c > 0) ? 1.f : 0.f;
}

// ---------------- K6: passB -- scatter g1 over compacted list2 (~72K edges) ----
__global__ void passB() {
    int i = blockIdx.x * blockDim.x + threadIdx.x;
    if (i >= n2 || i >= CAP2) return;
    int2 e = l2v[i];
    float4 a = __ldg(&g1v[e.x * 2]);
    float4 b = __ldg(&g1v[e.x * 2 + 1]);
    red_v4((float*)&g2v[e.y * 2], a);
    red_v4((float*)&g2v[e.y * 2 + 1], b);
}

// ---------------- K7: norm2 -- g2 = S2sum/cnt at plane1|O ----------------
__global__ void norm2() {
    int i = blockIdx.x * blockDim.x + threadIdx.x;
    if (i >= Nn) return;
    if (!tb1g(i)) return;
    float inv = 1.f / (float)max(cntv[i], 1);
    float4 a = g2v[i * 2], b = g2v[i * 2 + 1];
    a.x *= inv; a.y *= inv; a.z *= inv; a.w *= inv;
    b.x *= inv; b.y *= inv; b.z *= inv; b.w *= inv;
    g2v[i * 2] = a; g2v[i * 2 + 1] = b;
}

// ---------------- K8a/K8b: exact d2 correction (cold path) ----------------
__global__ void d2fixA() {
    if (any_zero == 0) return;
    int i = blockIdx.x * blockDim.x + threadIdx.x;
    if (i >= n2 || i >= CAP2) return;
    int2 e = l2v[i];
    if (cntv[e.x] == 0) atomicAdd(&zcv[e.y], 1);
}
__global__ void d2fixB() {
    if (any_zero == 0) return;
    int i = blockIdx.x * blockDim.x + threadIdx.x;
    if (i >= Nn) return;
    if (!tb1g(i)) return;
    int c = cntv[i];
    d2v[i] = (float)(c - zcv[i]) / (float)max(c, 1);
}

// ---------------- K9: passC -- layer-3 scatter over list68 (~2K edges) --------
__global__ void passC() {
    int i = blockIdx.x * blockDim.x + threadIdx.x;
    if (i >= n68 || i >= CAP68) return;
    int2 e = l68[i];
    int s = e.x, d = e.y;
    float4 a = g2v[s * 2], b = g2v[s * 2 + 1];
    atomicAdd(&out_acc[d * 9 + 0], a.x);
    atomicAdd(&out_acc[d * 9 + 1], a.y);
    atomicAdd(&out_acc[d * 9 + 2], a.z);
    atomicAdd(&out_acc[d * 9 + 3], a.w);
    atomicAdd(&out_acc[d * 9 + 4], b.x);
    atomicAdd(&out_acc[d * 9 + 5], b.y);
    atomicAdd(&out_acc[d * 9 + 6], b.z);
    atomicAdd(&out_acc[d * 9 + 7], b.w);
    atomicAdd(&out_acc[d * 9 + 8], d2v[s]);
}

// ---------------- K10: final combine ----------------
__global__ void final_kernel(float* __restrict__ out) {
    int t = threadIdx.x;
    if (t >= NOUT * 3) return;
    int i = t / 3, c = t % 3;
    const float* g0 = (const float*)g0v;
    const float* g1 = (const float*)g1v;
    const float* g2 = (const float*)g2v;
    int cn = cntv[i];
    float inv = 1.f / (float)max(cn, 1);
    float acc = 0.f;
#pragma unroll
    for (int f = 0; f < 8; f++) acc += g0[i * 8 + f] * Cmat[0 * 27 + f * 3 + c];
    acc += Cmat[0 * 27 + 8 * 3 + c];
#pragma unroll
    for (int f = 0; f < 8; f++) acc += g1[i * 8 + f] * Cmat[1 * 27 + f * 3 + c];
    acc += (cn > 0 ? 1.f : 0.f) * Cmat[1 * 27 + 8 * 3 + c];
#pragma unroll
    for (int f = 0; f < 8; f++) acc += g2[i * 8 + f] * Cmat[2 * 27 + f * 3 + c];
    acc += d2v[i] * Cmat[2 * 27 + 8 * 3 + c];
#pragma unroll
    for (int f = 0; f < 9; f++) acc += out_acc[i * 9 + f] * inv * Cmat[3 * 27 + f * 3 + c];
    out[t] = acc;
}

// ---------------- launch ----------------
extern "C" void kernel_launch(void* const* d_in, const int* in_sizes, int n_in,
                              void* d_out, int out_size) {
    const float* x      = (const float*)d_in[0];
    const int*   ei     = (const int*)d_in[1];
    const float* w_pos  = (const float*)d_in[2];
    const float* b_pos  = (const float*)d_in[3];
    const float* Wl1    = (const float*)d_in[4];
    const float* Wr1    = (const float*)d_in[5];
    const float* b1     = (const float*)d_in[6];
    const float* Wl2    = (const float*)d_in[7];
    const float* Wr2    = (const float*)d_in[8];
    const float* b2     = (const float*)d_in[9];
    const float* Wl3    = (const float*)d_in[10];
    const float* Wr3    = (const float*)d_in[11];
    const float* b3     = (const float*)d_in[12];
    float* out = (float*)d_out;

    int nodeBlocks = (Nn + 255) / 256;
    int edgeBlocks = (Ee / 4 + 255) / 256;          // 256-thread, 4 edges/thread
    int edgeBlocksW = (Ee / 4 + 1023) / 1024;       // 1024-thread, 4 edges/thread

    build_cmat<<<1, 160>>>(Wl1, Wr1, b1, Wl2, Wr2, b2, Wl3, Wr3, b3);
    init_kernel<<<nodeBlocks, 256>>>(x, w_pos, b_pos);
    scan1<<<edgeBlocks, 256>>>(ei);
    scan2s<<<edgeBlocksW, 1024>>>(ei);
    scan3s<<<edgeBlocksW, 1024>>>(ei);
    norm1<<<nodeBlocks, 256>>>();
    passB<<<CAP2 / 256, 256>>>();
    norm2<<<nodeBlocks, 256>>>();
    d2fixA<<<CAP2 / 256, 256>>>();
    d2fixB<<<nodeBlocks, 256>>>();
    passC<<<CAP68 / 256, 256>>>();
    final_kernel<<<1, 256>>>(out);
}

// round 8
// speedup vs baseline: 1.0280x; 1.0280x over previous
#include <cuda_runtime.h>

#define Nn 150000
#define Ee 4800000
#define NOUT 68
#define NW2 9375              // ceil(Nn/16), 2 bits per node
#define NW2P 9376             // padded to multiple of 4 for uint4 preload
#define CAP68 8192
#define SEG 64
#define SEGCAP 4096           // l2v total = 64*4096 = 262144 slots

// ---------------- device scratch (no allocation allowed) ----------------
__device__ __align__(16) float4 g0v[Nn * 2];   // augmented input features (8 dims)
__device__ __align__(16) float4 g1v[Nn * 2];   // S1sum -> layer-1 mean (masked nodes)
__device__ __align__(16) float4 g2v[Nn * 2];   // S2sum -> layer-2 mean (masked nodes)
__device__ int   cntv[Nn];        // in-degree (exact at masked nodes)
__device__ int   zcv[Nn];         // cold-path: # zero-degree in-neighbors
__device__ float d2v[Nn];         // const-column after 2 aggregations
__device__ int   any_zero;
__device__ __align__(16) unsigned bits12[NW2P]; // bit 2k: plane1 (S1); bit 2k+1: plane2 (S2)
__device__ int2  l68[CAP68];      // edges with dst < 68
__device__ int   n68;
__device__ int2  l2v[SEG * SEGCAP]; // edges with dst in S1 u [0,68), segmented
__device__ int   n2seg[SEG];
__device__ float out_acc[NOUT * 9];
__device__ float Cmat[4 * 27];

__device__ __forceinline__ bool tb1g(int v) {
    return (v < NOUT) || ((__ldg(&bits12[v >> 4]) >> ((v & 15) * 2)) & 1u);
}
__device__ __forceinline__ void red_v4(float* addr, float4 v) {
    asm volatile("red.global.add.v4.f32 [%0], {%1,%2,%3,%4};"
                 :: "l"(addr), "f"(v.x), "f"(v.y), "f"(v.z), "f"(v.w)
                 : "memory");
}

// ---------------- K0: collapsed 9x3 weight matrices ----------------
__global__ void build_cmat(const float* __restrict__ Wl1, const float* __restrict__ Wr1,
                           const float* __restrict__ b1,
                           const float* __restrict__ Wl2, const float* __restrict__ Wr2,
                           const float* __restrict__ b2,
                           const float* __restrict__ Wl3, const float* __restrict__ Wr3,
                           const float* __restrict__ b3) {
    __shared__ float T0[9 * 17], T1[9 * 17];
    __shared__ float U0[9 * 17], U1[9 * 17], U2[9 * 17];
    int t = threadIdx.x;
    int r = t / 17, c = t % 17;
    if (t < 9 * 17) {
        float wl, wr;
        if (r < 8) {
            wl = (c < 16) ? Wl1[r * 16 + c] : 0.f;
            wr = (c < 16) ? Wr1[r * 16 + c] : 0.f;
        } else {
            wl = 0.f;
            wr = (c < 16) ? b1[c] : 1.f;
        }
        T0[t] = wr;
        T1[t] = wl;
    }
    __syncthreads();
    if (t < 9 * 17) {
        float a0 = 0.f, a1 = 0.f, a2 = 0.f;
        for (int k = 0; k < 17; k++) {
            float wr2 = (k < 16) ? ((c < 16) ? Wr2[k * 16 + c] : 0.f)
                                 : ((c < 16) ? b2[c] : 1.f);
            float wl2 = (k < 16 && c < 16) ? Wl2[k * 16 + c] : 0.f;
            float t0 = T0[r * 17 + k], t1 = T1[r * 17 + k];
            a0 += t0 * wr2;
            a1 += t1 * wr2 + t0 * wl2;
            a2 += t1 * wl2;
        }
        U0[t] = a0; U1[t] = a1; U2[t] = a2;
    }
    __syncthreads();
    if (t < 27) {
        int rr = t / 3, cc = t % 3;
        float c0 = 0.f, c1 = 0.f, c2 = 0.f, c3 = 0.f;
        for (int k = 0; k < 17; k++) {
            float wr3 = (k < 16) ? Wr3[k * 3 + cc] : b3[cc];
            float wl3 = (k < 16) ? Wl3[k * 3 + cc] : 0.f;
            float u0 = U0[rr * 17 + k], u1 = U1[rr * 17 + k], u2 = U2[rr * 17 + k];
            c0 += u0 * wr3;
            c1 += u1 * wr3 + u0 * wl3;
            c2 += u2 * wr3 + u1 * wl3;
            c3 += u2 * wl3;
        }
        Cmat[0 * 27 + t] = c0;
        Cmat[1 * 27 + t] = c1;
        Cmat[2 * 27 + t] = c2;
        Cmat[3 * 27 + t] = c3;
    }
}

// ---------------- K1: init everything + compute g0 ----------------
__global__ void init_kernel(const float* __restrict__ x,
                            const float* __restrict__ w_pos,
                            const float* __restrict__ b_pos) {
    int i = blockIdx.x * blockDim.x + threadIdx.x;
    if (i >= Nn) return;
    cntv[i] = 0; zcv[i] = 0;
    float4 z = make_float4(0.f, 0.f, 0.f, 0.f);
    g1v[i * 2] = z; g1v[i * 2 + 1] = z;
    g2v[i * 2] = z; g2v[i * 2 + 1] = z;
    if (i < NW2P) bits12[i] = 0u;
    if (i < SEG) n2seg[i] = 0;
    if (i < NOUT) {
#pragma unroll
        for (int j = 0; j < 9; j++) out_acc[i * 9 + j] = 0.f;
    }
    if (i == 0) { n68 = 0; any_zero = 0; }
    float fi = (float)i;
    float g[8];
    g[0] = x[i * 3 + 0]; g[1] = x[i * 3 + 1]; g[2] = x[i * 3 + 2];
#pragma unroll
    for (int p = 0; p < 5; p++) g[3 + p] = tanhf(fi * __ldg(&w_pos[p]) + __ldg(&b_pos[p]));
    g0v[i * 2 + 0] = *(float4*)&g[0];
    g0v[i * 2 + 1] = *(float4*)&g[4];
}

// ---------------- K2: scan1 -- mark plane1, compact dst<68 (probe-free) --------
__global__ void scan1(const int* __restrict__ ei) {
    int t = blockIdx.x * blockDim.x + threadIdx.x;
    int base = t * 4;
    if (base >= Ee) return;
    int4 d4 = __ldg((const int4*)&ei[Ee + base]);
    int dd[4] = { d4.x, d4.y, d4.z, d4.w };
    bool anyhit = (dd[0] < NOUT) | (dd[1] < NOUT) | (dd[2] < NOUT) | (dd[3] < NOUT);
    if (!anyhit) return;
    int4 s4 = __ldg((const int4*)&ei[base]);
    int ss[4] = { s4.x, s4.y, s4.z, s4.w };
#pragma unroll
    for (int k = 0; k < 4; k++) {
        if (dd[k] < NOUT) {
            int s = ss[k];
            unsigned m = 1u << ((s & 15) * 2);
            if (!(__ldg(&bits12[s >> 4]) & m)) atomicOr(&bits12[s >> 4], m);
            int p = atomicAdd(&n68, 1);
            if (p < CAP68) l68[p] = make_int2(s, dd[k]);
        }
    }
}

// ---------------- K3: scan2 -- smem probe (plane1), segmented append, mark plane2
__global__ __launch_bounds__(512) void scan2s(const int* __restrict__ ei) {
    __shared__ __align__(16) unsigned smb[NW2P];   // 37.5 KB
    {
        uint4* d = (uint4*)smb;
        const uint4* s = (const uint4*)bits12;
        for (int j = threadIdx.x; j < NW2P / 4; j += 512) d[j] = __ldg(&s[j]);
    }
    __syncthreads();
    int t = blockIdx.x * 512 + threadIdx.x;
    int base = t * 4;
    if (base >= Ee) return;
    int4 d4 = __ldg((const int4*)&ei[Ee + base]);
    int dd[4] = { d4.x, d4.y, d4.z, d4.w };
    bool hh[4];
#pragma unroll
    for (int k = 0; k < 4; k++) {
        int d = dd[k];
        hh[k] = (d < NOUT) || ((smb[d >> 4] >> ((d & 15) * 2)) & 1u);
    }
    if (!(hh[0] | hh[1] | hh[2] | hh[3])) return;
    int4 s4 = __ldg((const int4*)&ei[base]);
    int ss[4] = { s4.x, s4.y, s4.z, s4.w };
    int seg = blockIdx.x & (SEG - 1);
#pragma unroll
    for (int k = 0; k < 4; k++) {
        if (hh[k]) {
            int s = ss[k];
            int p = atomicAdd(&n2seg[seg], 1);
            if (p < SEGCAP) l2v[seg * SEGCAP + p] = make_int2(s, dd[k]);
            unsigned m = 2u << ((s & 15) * 2);
            if (!(__ldg(&bits12[s >> 4]) & m)) atomicOr(&bits12[s >> 4], m);
        }
    }
}

// ---------------- K4: scan3 -- smem probe (both planes), masked count + scatter -
__global__ __launch_bounds__(512) void scan3s(const int* __restrict__ ei) {
    __shared__ __align__(16) unsigned smb[NW2P];
    {
        uint4* d = (uint4*)smb;
        const uint4* s = (const uint4*)bits12;
        for (int j = threadIdx.x; j < NW2P / 4; j += 512) d[j] = __ldg(&s[j]);
    }
    __syncthreads();
    int t = blockIdx.x * 512 + threadIdx.x;
    int base = t * 4;
    if (base >= Ee) return;
    int4 d4 = __ldg((const int4*)&ei[Ee + base]);
    int dd[4] = { d4.x, d4.y, d4.z, d4.w };
    bool ff[4], cc[4];
#pragma unroll
    for (int k = 0; k < 4; k++) {
        int d = dd[k];
        unsigned pr = (smb[d >> 4] >> ((d & 15) * 2)) & 3u;
        ff[k] = ((pr >> 1) & 1u) || (d < NOUT);
        cc[k] = ff[k] || (pr & 1u);
    }
    if (!(cc[0] | cc[1] | cc[2] | cc[3])) return;
    int4 s4 = __ldg((const int4*)&ei[base]);
    int ss[4] = { s4.x, s4.y, s4.z, s4.w };
#pragma unroll
    for (int k = 0; k < 4; k++) {
        if (cc[k]) atomicAdd(&cntv[dd[k]], 1);
        if (ff[k]) {
            int s = ss[k], d = dd[k];
            float4 a = __ldg(&g0v[s * 2]);
            float4 b = __ldg(&g0v[s * 2 + 1]);
            red_v4((float*)&g1v[d * 2], a);
            red_v4((float*)&g1v[d * 2 + 1], b);
        }
    }
}

// ---------------- K5: norm1 -- g1 = S1sum/cnt at plane2|O; d2 default ----------
__global__ void norm1() {
    int i = blockIdx.x * blockDim.x + threadIdx.x;
    if (i >= Nn) return;
    unsigned pr = (__ldg(&bits12[i >> 4]) >> ((i & 15) * 2)) & 3u;
    bool b2m = (pr >> 1) & 1u;
    int c = cntv[i];
    if (b2m || (i < NOUT)) {
        if (b2m && c == 0) any_zero = 1;
        float inv = 1.f / (float)max(c, 1);
        float4 a = g1v[i * 2], b = g1v[i * 2 + 1];
        a.x *= inv; a.y *= inv; a.z *= inv; a.w *= inv;
        b.x *= inv; b.y *= inv; b.z *= inv; b.w *= inv;
        g1v[i * 2] = a; g1v[i * 2 + 1] = b;
    }
    if ((pr & 1u) || (i < NOUT)) d2v[i] = (c > 0) ? 1.f : 0.f;
}

// ---------------- K6: passB -- scatter g1 over segmented list2 (~72K edges) ----
__global__ void passB() {
    int i = blockIdx.x * blockDim.x + threadIdx.x;   // over SEG*SEGCAP
    int seg = i >> 12;                // SEGCAP = 4096
    int off = i & (SEGCAP - 1);
    if (off >= n2seg[seg]) return;    // n2seg <= SEGCAP enforced at append
    int2 e = l2v[i];
    float4 a = __ldg(&g1v[e.x * 2]);
    float4 b = __ldg(&g1v[e.x * 2 + 1]);
    red_v4((float*)&g2v[e.y * 2], a);
    red_v4((float*)&g2v[e.y * 2 + 1], b);
}

// ---------------- K7: norm2 -- g2 = S2sum/cnt at plane1|O ----------------
__global__ void norm2() {
    int i = blockIdx.x * blockDim.x + threadIdx.x;
    if (i >= Nn) return;
    if (!tb1g(i)) return;
    float inv = 1.f / (float)max(cntv[i], 1);
    float4 a = g2v[i * 2], b = g2v[i * 2 + 1];
    a.x *= inv; a.y *= inv; a.z *= inv; a.w *= inv;
    b.x *= inv; b.y *= inv; b.z *= inv; b.w *= inv;
    g2v[i * 2] = a; g2v[i * 2 + 1] = b;
}

// ---------------- K8a/K8b: exact d2 correction (cold path) ----------------
__global__ void d2fixA() {
    if (any_zero == 0) return;
    int i = blockIdx.x * blockDim.x + threadIdx.x;
    int seg = i >> 12;
    int off = i & (SEGCAP - 1);
    if (off >= n2seg[seg]) return;
    int2 e = l2v[i];
    if (cntv[e.x] == 0) atomicAdd(&zcv[e.y], 1);
}
__global__ void d2fixB() {
    if (any_zero == 0) return;
    int i = blockIdx.x * blockDim.x + threadIdx.x;
    if (i >= Nn) return;
    if (!tb1g(i)) return;
    int c = cntv[i];
    d2v[i] = (float)(c - zcv[i]) / (float)max(c, 1);
}

// ---------------- K9: passC -- layer-3 scatter over list68 (~2K edges) --------
__global__ void passC() {
    int i = blockIdx.x * blockDim.x + threadIdx.x;
    if (i >= n68 || i >= CAP68) return;
    int2 e = l68[i];
    int s = e.x, d = e.y;
    float4 a = g2v[s * 2], b = g2v[s * 2 + 1];
    atomicAdd(&out_acc[d * 9 + 0], a.x);
    atomicAdd(&out_acc[d * 9 + 1], a.y);
    atomicAdd(&out_acc[d * 9 + 2], a.z);
    atomicAdd(&out_acc[d * 9 + 3], a.w);
    atomicAdd(&out_acc[d * 9 + 4], b.x);
    atomicAdd(&out_acc[d * 9 + 5], b.y);
    atomicAdd(&out_acc[d * 9 + 6], b.z);
    atomicAdd(&out_acc[d * 9 + 7], b.w);
    atomicAdd(&out_acc[d * 9 + 8], d2v[s]);
}

// ---------------- K10: final combine ----------------
__global__ void final_kernel(float* __restrict__ out) {
    int t = threadIdx.x;
    if (t >= NOUT * 3) return;
    int i = t / 3, c = t % 3;
    const float* g0 = (const float*)g0v;
    const float* g1 = (const float*)g1v;
    const float* g2 = (const float*)g2v;
    int cn = cntv[i];
    float inv = 1.f / (float)max(cn, 1);
    float acc = 0.f;
#pragma unroll
    for (int f = 0; f < 8; f++) acc += g0[i * 8 + f] * Cmat[0 * 27 + f * 3 + c];
    acc += Cmat[0 * 27 + 8 * 3 + c];
#pragma unroll
    for (int f = 0; f < 8; f++) acc += g1[i * 8 + f] * Cmat[1 * 27 + f * 3 + c];
    acc += (cn > 0 ? 1.f : 0.f) * Cmat[1 * 27 + 8 * 3 + c];
#pragma unroll
    for (int f = 0; f < 8; f++) acc += g2[i * 8 + f] * Cmat[2 * 27 + f * 3 + c];
    acc += d2v[i] * Cmat[2 * 27 + 8 * 3 + c];
#pragma unroll
    for (int f = 0; f < 9; f++) acc += out_acc[i * 9 + f] * inv * Cmat[3 * 27 + f * 3 + c];
    out[t] = acc;
}

// ---------------- launch ----------------
extern "C" void kernel_launch(void* const* d_in, const int* in_sizes, int n_in,
                              void* d_out, int out_size) {
    const float* x      = (const float*)d_in[0];
    const int*   ei     = (const int*)d_in[1];
    const float* w_pos  = (const float*)d_in[2];
    const float* b_pos  = (const float*)d_in[3];
    const float* Wl1    = (const float*)d_in[4];
    const float* Wr1    = (const float*)d_in[5];
    const float* b1     = (const float*)d_in[6];
    const float* Wl2    = (const float*)d_in[7];
    const float* Wr2    = (const float*)d_in[8];
    const float* b2     = (const float*)d_in[9];
    const float* Wl3    = (const float*)d_in[10];
    const float* Wr3    = (const float*)d_in[11];
    const float* b3     = (const float*)d_in[12];
    float* out = (float*)d_out;

    int nodeBlocks = (Nn + 255) / 256;
    int edgeBlocks = (Ee / 4 + 255) / 256;       // 256-thread, 4 edges/thread
    int edgeBlocks512 = (Ee / 4 + 511) / 512;    // 512-thread, 4 edges/thread
    int segBlocks = (SEG * SEGCAP) / 256;

    build_cmat<<<1, 160>>>(Wl1, Wr1, b1, Wl2, Wr2, b2, Wl3, Wr3, b3);
    init_kernel<<<nodeBlocks, 256>>>(x, w_pos, b_pos);
    scan1<<<edgeBlocks, 256>>>(ei);
    scan2s<<<edgeBlocks512, 512>>>(ei);
    scan3s<<<edgeBlocks512, 512>>>(ei);
    norm1<<<nodeBlocks, 256>>>();
    passB<<<segBlocks, 256>>>();
    norm2<<<nodeBlocks, 256>>>();
    d2fixA<<<segBlocks, 256>>>();
    d2fixB<<<nodeBlocks, 256>>>();
    passC<<<(CAP68 + 255) / 256, 256>>>();
    final_kernel<<<1, 256>>>(out);
}

// round 9
// speedup vs baseline: 1.0285x; 1.0005x over previous
#include <cuda_runtime.h>

#define Nn 150000
#define Ee 4800000
#define EQ (Ee / 4)           // quarter stream
#define NOUT 68
#define NW2 9375              // ceil(Nn/16), 2 bits per node
#define NW2P 9376             // padded for uint4 preload
#define CAP68 8192
#define SEG 64
#define SEGCAP 4096

// ---------------- device scratch (no allocation allowed) ----------------
__device__ __align__(16) float4 g0v[Nn * 2];
__device__ __align__(16) float4 g1v[Nn * 2];
__device__ __align__(16) float4 g2v[Nn * 2];
__device__ int   cntv[Nn];
__device__ int   zcv[Nn];
__device__ float d2v[Nn];
__device__ int   any_zero;
__device__ __align__(16) unsigned bits12[NW2P]; // bit 2k: plane1 (S1); 2k+1: plane2 (S2)
__device__ int2  l68[CAP68];
__device__ int   n68;
__device__ int2  l2v[SEG * SEGCAP];
__device__ int   n2seg[SEG];
__device__ float out_acc[NOUT * 9];
__device__ float Cmat[4 * 27];

__device__ __forceinline__ bool tb1g(int v) {
    return (v < NOUT) || ((__ldg(&bits12[v >> 4]) >> ((v & 15) * 2)) & 1u);
}
__device__ __forceinline__ void red_v4(float* addr, float4 v) {
    asm volatile("red.global.add.v4.f32 [%0], {%1,%2,%3,%4};"
                 :: "l"(addr), "f"(v.x), "f"(v.y), "f"(v.z), "f"(v.w)
                 : "memory");
}
__device__ __forceinline__ void red_or(unsigned* addr, unsigned v) {
    asm volatile("red.global.or.b32 [%0], %1;" :: "l"(addr), "r"(v) : "memory");
}
__device__ __forceinline__ void red_add1(int* addr) {
    asm volatile("red.global.add.s32 [%0], 1;" :: "l"(addr) : "memory");
}

// ---------------- K0: collapsed 9x3 weight matrices ----------------
__global__ void build_cmat(const float* __restrict__ Wl1, const float* __restrict__ Wr1,
                           const float* __restrict__ b1,
                           const float* __restrict__ Wl2, const float* __restrict__ Wr2,
                           const float* __restrict__ b2,
                           const float* __restrict__ Wl3, const float* __restrict__ Wr3,
                           const float* __restrict__ b3) {
    __shared__ float T0[9 * 17], T1[9 * 17];
    __shared__ float U0[9 * 17], U1[9 * 17], U2[9 * 17];
    int t = threadIdx.x;
    int r = t / 17, c = t % 17;
    if (t < 9 * 17) {
        float wl, wr;
        if (r < 8) {
            wl = (c < 16) ? Wl1[r * 16 + c] : 0.f;
            wr = (c < 16) ? Wr1[r * 16 + c] : 0.f;
        } else {
            wl = 0.f;
            wr = (c < 16) ? b1[c] : 1.f;
        }
        T0[t] = wr;
        T1[t] = wl;
    }
    __syncthreads();
    if (t < 9 * 17) {
        float a0 = 0.f, a1 = 0.f, a2 = 0.f;
        for (int k = 0; k < 17; k++) {
            float wr2 = (k < 16) ? ((c < 16) ? Wr2[k * 16 + c] : 0.f)
                                 : ((c < 16) ? b2[c] : 1.f);
            float wl2 = (k < 16 && c < 16) ? Wl2[k * 16 + c] : 0.f;
            float t0 = T0[r * 17 + k], t1 = T1[r * 17 + k];
            a0 += t0 * wr2;
            a1 += t1 * wr2 + t0 * wl2;
            a2 += t1 * wl2;
        }
        U0[t] = a0; U1[t] = a1; U2[t] = a2;
    }
    __syncthreads();
    if (t < 27) {
        int rr = t / 3, cc = t % 3;
        float c0 = 0.f, c1 = 0.f, c2 = 0.f, c3 = 0.f;
        for (int k = 0; k < 17; k++) {
            float wr3 = (k < 16) ? Wr3[k * 3 + cc] : b3[cc];
            float wl3 = (k < 16) ? Wl3[k * 3 + cc] : 0.f;
            float u0 = U0[rr * 17 + k], u1 = U1[rr * 17 + k], u2 = U2[rr * 17 + k];
            c0 += u0 * wr3;
            c1 += u1 * wr3 + u0 * wl3;
            c2 += u2 * wr3 + u1 * wl3;
            c3 += u2 * wl3;
        }
        Cmat[0 * 27 + t] = c0;
        Cmat[1 * 27 + t] = c1;
        Cmat[2 * 27 + t] = c2;
        Cmat[3 * 27 + t] = c3;
    }
}

// ---------------- K1: init everything + compute g0 ----------------
__global__ void init_kernel(const float* __restrict__ x,
                            const float* __restrict__ w_pos,
                            const float* __restrict__ b_pos) {
    int i = blockIdx.x * blockDim.x + threadIdx.x;
    if (i >= Nn) return;
    cntv[i] = 0; zcv[i] = 0;
    float4 z = make_float4(0.f, 0.f, 0.f, 0.f);
    g1v[i * 2] = z; g1v[i * 2 + 1] = z;
    g2v[i * 2] = z; g2v[i * 2 + 1] = z;
    if (i < NW2P) bits12[i] = 0u;
    if (i < SEG) n2seg[i] = 0;
    if (i < NOUT) {
#pragma unroll
        for (int j = 0; j < 9; j++) out_acc[i * 9 + j] = 0.f;
    }
    if (i == 0) { n68 = 0; any_zero = 0; }
    float fi = (float)i;
    float g[8];
    g[0] = x[i * 3 + 0]; g[1] = x[i * 3 + 1]; g[2] = x[i * 3 + 2];
#pragma unroll
    for (int p = 0; p < 5; p++) g[3 + p] = tanhf(fi * __ldg(&w_pos[p]) + __ldg(&b_pos[p]));
    g0v[i * 2 + 0] = *(float4*)&g[0];
    g0v[i * 2 + 1] = *(float4*)&g[4];
}

// ---------------- K2: scan1 -- 16 edges/thread via 4 quartered streams ---------
__global__ __launch_bounds__(512) void scan1(const int* __restrict__ ei) {
    int t = blockIdx.x * 512 + threadIdx.x;
    int base = t * 4;
    if (base >= EQ) return;
    const int* dstp = ei + Ee;
    int4 D[4];
#pragma unroll
    for (int q = 0; q < 4; q++) D[q] = __ldg((const int4*)&dstp[q * EQ + base]);
    unsigned hit[4]; bool any = false;
#pragma unroll
    for (int q = 0; q < 4; q++) {
        int dd[4] = { D[q].x, D[q].y, D[q].z, D[q].w };
        unsigned h = 0;
#pragma unroll
        for (int k = 0; k < 4; k++) h |= (dd[k] < NOUT) ? (1u << k) : 0u;
        hit[q] = h; any |= (h != 0);
    }
    if (!any) return;
#pragma unroll
    for (int q = 0; q < 4; q++) {
        if (!hit[q]) continue;
        int4 S = __ldg((const int4*)&ei[q * EQ + base]);
        int ss[4] = { S.x, S.y, S.z, S.w };
        int dd[4] = { D[q].x, D[q].y, D[q].z, D[q].w };
#pragma unroll
        for (int k = 0; k < 4; k++) {
            if ((hit[q] >> k) & 1u) {
                int s = ss[k];
                red_or(&bits12[s >> 4], 1u << ((s & 15) * 2));
                int p = atomicAdd(&n68, 1);
                if (p < CAP68) l68[p] = make_int2(s, dd[k]);
            }
        }
    }
}

// ---------------- K3: scan2 -- smem probe plane1, append l2v, mark plane2 ------
__global__ __launch_bounds__(512) void scan2s(const int* __restrict__ ei) {
    __shared__ __align__(16) unsigned smb[NW2P];
    {
        uint4* d = (uint4*)smb;
        const uint4* s = (const uint4*)bits12;
        for (int j = threadIdx.x; j < NW2P / 4; j += 512) d[j] = __ldg(&s[j]);
    }
    __syncthreads();
    int t = blockIdx.x * 512 + threadIdx.x;
    int base = t * 4;
    if (base >= EQ) return;
    const int* dstp = ei + Ee;
    int4 D[4];
#pragma unroll
    for (int q = 0; q < 4; q++) D[q] = __ldg((const int4*)&dstp[q * EQ + base]);
    unsigned hit[4]; bool any = false;
#pragma unroll
    for (int q = 0; q < 4; q++) {
        int dd[4] = { D[q].x, D[q].y, D[q].z, D[q].w };
        unsigned h = 0;
#pragma unroll
        for (int k = 0; k < 4; k++) {
            int d = dd[k];
            bool m = (d < NOUT) || ((smb[d >> 4] >> ((d & 15) * 2)) & 1u);
            h |= m ? (1u << k) : 0u;
        }
        hit[q] = h; any |= (h != 0);
    }
    if (!any) return;
    int seg = (blockIdx.x * 16 + (threadIdx.x >> 5)) & (SEG - 1);
#pragma unroll
    for (int q = 0; q < 4; q++) {
        if (!hit[q]) continue;
        int4 S = __ldg((const int4*)&ei[q * EQ + base]);
        int ss[4] = { S.x, S.y, S.z, S.w };
        int dd[4] = { D[q].x, D[q].y, D[q].z, D[q].w };
#pragma unroll
        for (int k = 0; k < 4; k++) {
            if ((hit[q] >> k) & 1u) {
                int s = ss[k];
                red_or(&bits12[s >> 4], 2u << ((s & 15) * 2));
                int p = atomicAdd(&n2seg[seg], 1);
                if (p < SEGCAP) l2v[seg * SEGCAP + p] = make_int2(s, dd[k]);
            }
        }
    }
}

// ---------------- K4: scan3 -- smem probe both planes, count + g0 scatter ------
__global__ __launch_bounds__(512) void scan3s(const int* __restrict__ ei) {
    __shared__ __align__(16) unsigned smb[NW2P];
    {
        uint4* d = (uint4*)smb;
        const uint4* s = (const uint4*)bits12;
        for (int j = threadIdx.x; j < NW2P / 4; j += 512) d[j] = __ldg(&s[j]);
    }
    __syncthreads();
    int t = blockIdx.x * 512 + threadIdx.x;
    int base = t * 4;
    if (base >= EQ) return;
    const int* dstp = ei + Ee;
    int4 D[4];
#pragma unroll
    for (int q = 0; q < 4; q++) D[q] = __ldg((const int4*)&dstp[q * EQ + base]);
    unsigned fm[4], cm[4]; bool anyc = false;
#pragma unroll
    for (int q = 0; q < 4; q++) {
        int dd[4] = { D[q].x, D[q].y, D[q].z, D[q].w };
        unsigned f = 0, c = 0;
#pragma unroll
        for (int k = 0; k < 4; k++) {
            int d = dd[k];
            unsigned pr = (smb[d >> 4] >> ((d & 15) * 2)) & 3u;
            bool fk = ((pr >> 1) & 1u) || (d < NOUT);
            bool ck = fk || (pr & 1u);
            f |= fk ? (1u << k) : 0u;
            c |= ck ? (1u << k) : 0u;
        }
        fm[q] = f; cm[q] = c; anyc |= (c != 0);
    }
    if (!anyc) return;
#pragma unroll
    for (int q = 0; q < 4; q++) {
        if (!cm[q]) continue;
        int4 S = __ldg((const int4*)&ei[q * EQ + base]);
        int ss[4] = { S.x, S.y, S.z, S.w };
        int dd[4] = { D[q].x, D[q].y, D[q].z, D[q].w };
#pragma unroll
        for (int k = 0; k < 4; k++) {
            if ((cm[q] >> k) & 1u) red_add1(&cntv[dd[k]]);
            if ((fm[q] >> k) & 1u) {
                int s = ss[k], d = dd[k];
                float4 a = __ldg(&g0v[s * 2]);
                float4 b = __ldg(&g0v[s * 2 + 1]);
                red_v4((float*)&g1v[d * 2], a);
                red_v4((float*)&g1v[d * 2 + 1], b);
            }
        }
    }
}

// ---------------- K5: norm1 ----------------
__global__ void norm1() {
    int i = blockIdx.x * blockDim.x + threadIdx.x;
    if (i >= Nn) return;
    unsigned pr = (__ldg(&bits12[i >> 4]) >> ((i & 15) * 2)) & 3u;
    bool b2m = (pr >> 1) & 1u;
    int c = cntv[i];
    if (b2m || (i < NOUT)) {
        if (b2m && c == 0) any_zero = 1;
        float inv = 1.f / (float)max(c, 1);
        float4 a = g1v[i * 2], b = g1v[i * 2 + 1];
        a.x *= inv; a.y *= inv; a.z *= inv; a.w *= inv;
        b.x *= inv; b.y *= inv; b.z *= inv; b.w *= inv;
        g1v[i * 2] = a; g1v[i * 2 + 1] = b;
    }
    if ((pr & 1u) || (i < NOUT)) d2v[i] = (c > 0) ? 1.f : 0.f;
}

// ---------------- K6: passB -- scatter g1 over segmented list2 ----------------
__global__ void passB() {
    int i = blockIdx.x * blockDim.x + threadIdx.x;
    int seg = i >> 12;
    int off = i & (SEGCAP - 1);
    if (off >= n2seg[seg]) return;
    int2 e = l2v[i];
    float4 a = __ldg(&g1v[e.x * 2]);
    float4 b = __ldg(&g1v[e.x * 2 + 1]);
    red_v4((float*)&g2v[e.y * 2], a);
    red_v4((float*)&g2v[e.y * 2 + 1], b);
}

// ---------------- K7: norm2 ----------------
__global__ void norm2() {
    int i = blockIdx.x * blockDim.x + threadIdx.x;
    if (i >= Nn) return;
    if (!tb1g(i)) return;
    float inv = 1.f / (float)max(cntv[i], 1);
    float4 a = g2v[i * 2], b = g2v[i * 2 + 1];
    a.x *= inv; a.y *= inv; a.z *= inv; a.w *= inv;
    b.x *= inv; b.y *= inv; b.z *= inv; b.w *= inv;
    g2v[i * 2] = a; g2v[i * 2 + 1] = b;
}

// ---------------- K8a/K8b: exact d2 correction (cold path) ----------------
__global__ void d2fixA() {
    if (any_zero == 0) return;
    int i = blockIdx.x * blockDim.x + threadIdx.x;
    int seg = i >> 12;
    int off = i & (SEGCAP - 1);
    if (off >= n2seg[seg]) return;
    int2 e = l2v[i];
    if (cntv[e.x] == 0) atomicAdd(&zcv[e.y], 1);
}
__global__ void d2fixB() {
    if (any_zero == 0) return;
    int i = blockIdx.x * blockDim.x + threadIdx.x;
    if (i >= Nn) return;
    if (!tb1g(i)) return;
    int c = cntv[i];
    d2v[i] = (float)(c - zcv[i]) / (float)max(c, 1);
}

// ---------------- K9: passC ----------------
__global__ void passC() {
    int i = blockIdx.x * blockDim.x + threadIdx.x;
    if (i >= n68 || i >= CAP68) return;
    int2 e = l68[i];
    int s = e.x, d = e.y;
    float4 a = g2v[s * 2], b = g2v[s * 2 + 1];
    atomicAdd(&out_acc[d * 9 + 0], a.x);
    atomicAdd(&out_acc[d * 9 + 1], a.y);
    atomicAdd(&out_acc[d * 9 + 2], a.z);
    atomicAdd(&out_acc[d * 9 + 3], a.w);
    atomicAdd(&out_acc[d * 9 + 4], b.x);
    atomicAdd(&out_acc[d * 9 + 5], b.y);
    atomicAdd(&out_acc[d * 9 + 6], b.z);
    atomicAdd(&out_acc[d * 9 + 7], b.w);
    atomicAdd(&out_acc[d * 9 + 8], d2v[s]);
}

// ---------------- K10: final combine ----------------
__global__ void final_kernel(float* __restrict__ out) {
    int t = threadIdx.x;
    if (t >= NOUT * 3) return;
    int i = t / 3, c = t % 3;
    const float* g0 = (const float*)g0v;
    const float* g1 = (const float*)g1v;
    const float* g2 = (const float*)g2v;
    int cn = cntv[i];
    float inv = 1.f / (float)max(cn, 1);
    float acc = 0.f;
#pragma unroll
    for (int f = 0; f < 8; f++) acc += g0[i * 8 + f] * Cmat[0 * 27 + f * 3 + c];
    acc += Cmat[0 * 27 + 8 * 3 + c];
#pragma unroll
    for (int f = 0; f < 8; f++) acc += g1[i * 8 + f] * Cmat[1 * 27 + f * 3 + c];
    acc += (cn > 0 ? 1.f : 0.f) * Cmat[1 * 27 + 8 * 3 + c];
#pragma unroll
    for (int f = 0; f < 8; f++) acc += g2[i * 8 + f] * Cmat[2 * 27 + f * 3 + c];
    acc += d2v[i] * Cmat[2 * 27 + 8 * 3 + c];
#pragma unroll
    for (int f = 0; f < 9; f++) acc += out_acc[i * 9 + f] * inv * Cmat[3 * 27 + f * 3 + c];
    out[t] = acc;
}

// ---------------- launch ----------------
extern "C" void kernel_launch(void* const* d_in, const int* in_sizes, int n_in,
                              void* d_out, int out_size) {
    const float* x      = (const float*)d_in[0];
    const int*   ei     = (const int*)d_in[1];
    const float* w_pos  = (const float*)d_in[2];
    const float* b_pos  = (const float*)d_in[3];
    const float* Wl1    = (const float*)d_in[4];
    const float* Wr1    = (const float*)d_in[5];
    const float* b1     = (const float*)d_in[6];
    const float* Wl2    = (const float*)d_in[7];
    const float* Wr2    = (const float*)d_in[8];
    const float* b2     = (const float*)d_in[9];
    const float* Wl3    = (const float*)d_in[10];
    const float* Wr3    = (const float*)d_in[11];
    const float* b3     = (const float*)d_in[12];
    float* out = (float*)d_out;

    int nodeBlocks = (Nn + 255) / 256;
    int qBlocks = (EQ / 4 + 511) / 512;          // 16 edges/thread, 4 quarters
    int segBlocks = (SEG * SEGCAP) / 256;

    build_cmat<<<1, 160>>>(Wl1, Wr1, b1, Wl2, Wr2, b2, Wl3, Wr3, b3);
    init_kernel<<<nodeBlocks, 256>>>(x, w_pos, b_pos);
    scan1<<<qBlocks, 512>>>(ei);
    scan2s<<<qBlocks, 512>>>(ei);
    scan3s<<<qBlocks, 512>>>(ei);
    norm1<<<nodeBlocks, 256>>>();
    passB<<<segBlocks, 256>>>();
    norm2<<<nodeBlocks, 256>>>();
    d2fixA<<<segBlocks, 256>>>();
    d2fixB<<<nodeBlocks, 256>>>();
    passC<<<(CAP68 + 255) / 256, 256>>>();
    final_kernel<<<1, 256>>>(out);
}